// round 17
// baseline (speedup 1.0000x reference)
#include <cuda_runtime.h>
#include <cuda_fp16.h>
#include <math.h>
#include <stdint.h>

// ---------------- problem constants ----------------
constexpr int B_   = 32;
constexpr int C_   = 256;
constexpr int N_   = 1024;
constexpr int C3_  = 768;
constexpr int MTOT = B_ * N_;   // 32768

// ---------------- scratch ----------------
__device__ float2 g_ps [C_ * 16];              // per (channel, slice) partial sums
__device__ __half g_t  [(size_t)MTOT * C_];    // [B,N,C]
__device__ __half g_kqv[(size_t)MTOT * C3_];   // [B,N,3C]
__device__ __half g_s  [(size_t)B_ * N_ * N_]; // [B,N,N] exp(scores/16)
__device__ __half g_vp [(size_t)B_ * C_ * N_]; // [B,C,N]  Vp^T = Wp @ V^T
__device__ __half g_wk [(size_t)C3_ * C_];     // W_kqv fp16
__device__ __half g_wp [(size_t)C_ * C_];      // W_proj fp16
__device__ float  g_pl [(size_t)B_ * 8 * N_];  // per-tile row expsum

// ---------------- PTX helpers ----------------
__device__ __forceinline__ uint32_t smem_u32(const void* p) {
    return (uint32_t)__cvta_generic_to_shared(p);
}
__device__ __forceinline__ void mma_fp16(float c[4], const uint32_t a[4], const uint32_t b[2]) {
    asm volatile(
        "mma.sync.aligned.m16n8k16.row.col.f32.f16.f16.f32 "
        "{%0,%1,%2,%3}, {%4,%5,%6,%7}, {%8,%9}, {%0,%1,%2,%3};"
        : "+f"(c[0]), "+f"(c[1]), "+f"(c[2]), "+f"(c[3])
        : "r"(a[0]), "r"(a[1]), "r"(a[2]), "r"(a[3]), "r"(b[0]), "r"(b[1]));
}
#define LDSM_X4(r0, r1, r2, r3, addr) \
    asm volatile("ldmatrix.sync.aligned.m8n8.x4.shared.b16 {%0,%1,%2,%3}, [%4];" \
        : "=r"(r0), "=r"(r1), "=r"(r2), "=r"(r3) : "r"(addr))
#define CP_ASYNC16(dst, src) \
    asm volatile("cp.async.cg.shared.global [%0], [%1], 16;" :: "r"(dst), "l"(src))
#define CP_ASYNC_COMMIT() asm volatile("cp.async.commit_group;" ::: "memory")
#define CP_ASYNC_WAIT(n)  asm volatile("cp.async.wait_group %0;" :: "n"(n) : "memory")

// ---------------- shared GEMM geometry ----------------
constexpr int NT          = 256;
constexpr int ROW_B       = 144;                 // operand tile row stride (bytes)
constexpr int TILE_BYTES  = 128 * ROW_B;         // 18432
constexpr int STAGE_BYTES = 2 * TILE_BYTES;      // 36864
constexpr int SMEM_DYN    = 3 * STAGE_BYTES + 512; // 111104 (2 CTAs/SM)
constexpr int PS_ROW      = 136;                 // staging row stride (halves)
constexpr int IL_OFF      = 3 * STAGE_BYTES / 4; // float offset of il buffer

// mainloop macro body shared by all kernels (identical structure)
#define GEMM_MAINLOOP(K)                                                       \
    float acc[4][4][4] = {};                                                   \
    {                                                                          \
        const int nk = (K) >> 6;                                               \
        load_stage(0, 0);                                                      \
        load_stage(1, 1);                                                      \
        for (int ks = 0; ks < nk; ks++) {                                      \
            CP_ASYNC_WAIT(1);                                                  \
            __syncthreads();                                                   \
            if (ks + 2 < nk) load_stage((ks + 2) % 3, ks + 2);                 \
            else             CP_ASYNC_COMMIT();                                \
            const uint32_t abase = smb + (ks % 3) * STAGE_BYTES;               \
            const uint32_t bbase = abase + TILE_BYTES;                         \
            _Pragma("unroll")                                                  \
            for (int kk = 0; kk < 4; kk++) {                                   \
                uint32_t af[4][4], bf[4][2];                                   \
                _Pragma("unroll")                                              \
                for (int tm = 0; tm < 4; tm++) {                               \
                    LDSM_X4(af[tm][0], af[tm][1], af[tm][2], af[tm][3],        \
                            abase + a_lo + (uint32_t)(tm * 16 * ROW_B + kk * 32)); \
                }                                                              \
                _Pragma("unroll")                                              \
                for (int tnp = 0; tnp < 2; tnp++) {                            \
                    LDSM_X4(bf[2*tnp][0], bf[2*tnp][1], bf[2*tnp+1][0], bf[2*tnp+1][1], \
                            bbase + b_lo + (uint32_t)(tnp * 16 * ROW_B + kk * 32)); \
                }                                                              \
                _Pragma("unroll")                                              \
                for (int tm = 0; tm < 4; tm++)                                 \
                    _Pragma("unroll")                                          \
                    for (int tn = 0; tn < 4; tn++)                             \
                        mma_fp16(acc[tm][tn], af[tm], bf[tn]);                 \
            }                                                                  \
        }                                                                      \
    }

// ---------------- KQV GEMM: kqv = t @ wk^T + b_kqv ----------------
__global__ __launch_bounds__(NT, 2)
void kqv_kernel(const float* __restrict__ bias) {
    extern __shared__ float sm[];
    const int tid  = threadIdx.x;
    const int lane = tid & 31;
    const int warp = tid >> 5;
    const int wm   = warp & 1;
    const int wn   = warp >> 1;
    const int g    = lane >> 2;
    const int q    = lane & 3;
    const int m0   = blockIdx.y * 128;
    const int n0   = blockIdx.x * 128;
    const uint32_t smb = smem_u32(sm);

    const __half* Ab = g_t;
    const __half* Bb = g_wk;
    const int lda = C_, ldb = C_;

    const uint32_t a_lo =
        (uint32_t)((wm * 64 + (lane & 15)) * ROW_B + (lane >> 4) * 16);
    const uint32_t b_lo =
        (uint32_t)((wn * 32 + ((lane >> 4) & 1) * 8 + (lane & 7)) * ROW_B +
                   ((lane >> 3) & 1) * 16);

    auto load_stage = [&](int slot, int kc) {
        const uint32_t abase = smb + slot * STAGE_BYTES;
        const uint32_t bbase = abase + TILE_BYTES;
        const __half* Asrc = Ab + (size_t)m0 * lda + kc * 64;
        #pragma unroll
        for (int j = 0; j < 4; j++) {
            int i = tid + j * NT;
            int row = i >> 3, kg = i & 7;
            CP_ASYNC16(abase + (uint32_t)(row * ROW_B + kg * 16),
                       Asrc + (size_t)row * lda + kg * 8);
        }
        const __half* Bsrc = Bb + (size_t)n0 * ldb + kc * 64;
        #pragma unroll
        for (int j = 0; j < 4; j++) {
            int i = tid + j * NT;
            int row = i >> 3, kg = i & 7;
            CP_ASYNC16(bbase + (uint32_t)(row * ROW_B + kg * 16),
                       Bsrc + (size_t)row * ldb + kg * 8);
        }
        CP_ASYNC_COMMIT();
    };

    GEMM_MAINLOOP(C_)

    // standard coalesced epilogue with bias (bias hoisted per-tn)
    __half* ps = (__half*)sm;
    __syncthreads();
    float bh0[4], bh1[4];
    #pragma unroll
    for (int tn = 0; tn < 4; tn++) {
        const int cl = wn * 32 + tn * 8 + 2 * q;
        bh0[tn] = __ldg(&bias[n0 + cl]);
        bh1[tn] = __ldg(&bias[n0 + cl + 1]);
    }
    #pragma unroll
    for (int tm = 0; tm < 4; tm++) {
        const int r = wm * 64 + tm * 16 + g;
        #pragma unroll
        for (int tn = 0; tn < 4; tn++) {
            const int cl = wn * 32 + tn * 8 + 2 * q;
            __half2 v0 = __floats2half2_rn(acc[tm][tn][0] + bh0[tn], acc[tm][tn][1] + bh1[tn]);
            __half2 v1 = __floats2half2_rn(acc[tm][tn][2] + bh0[tn], acc[tm][tn][3] + bh1[tn]);
            *reinterpret_cast<__half2*>(&ps[r * PS_ROW + cl])       = v0;
            *reinterpret_cast<__half2*>(&ps[(r + 8) * PS_ROW + cl]) = v1;
        }
    }
    __syncthreads();
    #pragma unroll
    for (int it = 0; it < 8; it++) {
        const int idx = tid + it * 256;
        const int row = idx >> 4;
        const int seg = idx & 15;
        uint4 v = *reinterpret_cast<uint4*>(&ps[row * PS_ROW + seg * 8]);
        *reinterpret_cast<uint4*>(&g_kqv[(size_t)(m0 + row) * C3_ + n0 + seg * 8]) = v;
    }
}

// ------- merged QK + VPT kernel: grid (10, 8, 32) --------------------------
__global__ __launch_bounds__(NT, 2)
void qk_vpt_kernel() {
    extern __shared__ float sm[];
    const int tid  = threadIdx.x;
    const int lane = tid & 31;
    const int warp = tid >> 5;
    const int wm   = warp & 1;
    const int wn   = warp >> 1;
    const int g    = lane >> 2;
    const int q    = lane & 3;
    const int bz   = blockIdx.z;
    const bool isqk = (blockIdx.x < 8);
    const uint32_t smb = smem_u32(sm);

    int m0, n0, lda, ldb;
    const __half *Ab, *Bb;
    if (isqk) {
        m0 = blockIdx.y * 128;
        n0 = blockIdx.x * 128;
        Ab = g_kqv + (size_t)bz * N_ * C3_;           // q
        Bb = g_kqv + (size_t)bz * N_ * C3_ + 256;     // k
        lda = C3_; ldb = C3_;
    } else {
        m0 = (blockIdx.x - 8) * 128;                  // co tile
        n0 = blockIdx.y * 128;                        // key tile
        Ab = g_wp;
        Bb = g_kqv + (size_t)bz * N_ * C3_ + 512;     // v
        lda = C_; ldb = C3_;
    }

    const uint32_t a_lo =
        (uint32_t)((wm * 64 + (lane & 15)) * ROW_B + (lane >> 4) * 16);
    const uint32_t b_lo =
        (uint32_t)((wn * 32 + ((lane >> 4) & 1) * 8 + (lane & 7)) * ROW_B +
                   ((lane >> 3) & 1) * 16);

    auto load_stage = [&](int slot, int kc) {
        const uint32_t abase = smb + slot * STAGE_BYTES;
        const uint32_t bbase = abase + TILE_BYTES;
        const __half* Asrc = Ab + (size_t)m0 * lda + kc * 64;
        #pragma unroll
        for (int j = 0; j < 4; j++) {
            int i = tid + j * NT;
            int row = i >> 3, kg = i & 7;
            CP_ASYNC16(abase + (uint32_t)(row * ROW_B + kg * 16),
                       Asrc + (size_t)row * lda + kg * 8);
        }
        const __half* Bsrc = Bb + (size_t)n0 * ldb + kc * 64;
        #pragma unroll
        for (int j = 0; j < 4; j++) {
            int i = tid + j * NT;
            int row = i >> 3, kg = i & 7;
            CP_ASYNC16(bbase + (uint32_t)(row * ROW_B + kg * 16),
                       Bsrc + (size_t)row * ldb + kg * 8);
        }
        CP_ASYNC_COMMIT();
    };

    GEMM_MAINLOOP(C_)

    __half* ps   = (__half*)sm;
    float*  redl = sm + 16384;
    __syncthreads();

    if (isqk) {
        // exp via ex2.approx.f16x2: e = 2^(s * log2e / 16)
        const float alpha2 = 0.0625f * 1.44269504089f;
        #pragma unroll
        for (int tm = 0; tm < 4; tm++) {
            const int r = wm * 64 + tm * 16 + g;
            float s0 = 0.f, s1 = 0.f;
            #pragma unroll
            for (int tn = 0; tn < 4; tn++) {
                const int cl = wn * 32 + tn * 8 + 2 * q;
                __half2 a0 = __floats2half2_rn(acc[tm][tn][0] * alpha2,
                                               acc[tm][tn][1] * alpha2);
                __half2 a1 = __floats2half2_rn(acc[tm][tn][2] * alpha2,
                                               acc[tm][tn][3] * alpha2);
                __half2 e0 = h2exp2(a0);
                __half2 e1 = h2exp2(a1);
                float2 f0 = __half22float2(e0);
                float2 f1 = __half22float2(e1);
                s0 += f0.x + f0.y;
                s1 += f1.x + f1.y;
                *reinterpret_cast<__half2*>(&ps[r * PS_ROW + cl])       = e0;
                *reinterpret_cast<__half2*>(&ps[(r + 8) * PS_ROW + cl]) = e1;
            }
            s0 += __shfl_xor_sync(~0u, s0, 1);
            s0 += __shfl_xor_sync(~0u, s0, 2);
            s1 += __shfl_xor_sync(~0u, s1, 1);
            s1 += __shfl_xor_sync(~0u, s1, 2);
            if (q == 0) {
                redl[wn * 128 + r]     = s0;
                redl[wn * 128 + r + 8] = s1;
            }
        }
    } else {
        #pragma unroll
        for (int tm = 0; tm < 4; tm++) {
            const int r = wm * 64 + tm * 16 + g;
            #pragma unroll
            for (int tn = 0; tn < 4; tn++) {
                const int cl = wn * 32 + tn * 8 + 2 * q;
                *reinterpret_cast<__half2*>(&ps[r * PS_ROW + cl]) =
                    __floats2half2_rn(acc[tm][tn][0], acc[tm][tn][1]);
                *reinterpret_cast<__half2*>(&ps[(r + 8) * PS_ROW + cl]) =
                    __floats2half2_rn(acc[tm][tn][2], acc[tm][tn][3]);
            }
        }
    }
    __syncthreads();

    __half* Cb = isqk ? (g_s  + (size_t)bz * N_ * N_)
                      : (g_vp + (size_t)bz * C_ * N_);
    const int ldc = N_;
    #pragma unroll
    for (int it = 0; it < 8; it++) {
        const int idx = tid + it * 256;
        const int row = idx >> 4;
        const int seg = idx & 15;
        uint4 v = *reinterpret_cast<uint4*>(&ps[row * PS_ROW + seg * 8]);
        *reinterpret_cast<uint4*>(&Cb[(size_t)(m0 + row) * ldc + n0 + seg * 8]) = v;
    }

    if (isqk && tid < 128) {
        float l = redl[tid] + redl[128 + tid] + redl[256 + tid] + redl[384 + tid];
        g_pl[((size_t)bz * 8 + blockIdx.x) * N_ + m0 + tid] = l;
    }
}

// ------- AVP kernel: out[b,co,n] = (expS @ Vp^T)^T / l + b_proj + x --------
__global__ __launch_bounds__(NT, 2)
void avp_kernel(const float* __restrict__ bias, float* __restrict__ Cm,
                const float* __restrict__ xr) {
    extern __shared__ float sm[];
    const int tid  = threadIdx.x;
    const int lane = tid & 31;
    const int warp = tid >> 5;
    const int wm   = warp & 1;
    const int wn   = warp >> 1;
    const int g    = lane >> 2;
    const int q    = lane & 3;
    const int bz   = blockIdx.z;
    const int m0   = blockIdx.y * 128;   // q rows
    const int n0   = blockIdx.x * 128;   // co
    const uint32_t smb = smem_u32(sm);

    float* sm_il = sm + IL_OFF;
    if (tid < 128) {
        float l = 0.f;
        #pragma unroll
        for (int t = 0; t < 8; t++)
            l += g_pl[((size_t)bz * 8 + t) * N_ + m0 + tid];
        sm_il[tid] = 1.0f / l;
    }

    const __half* Ab = g_s  + (size_t)bz * N_ * N_;
    const __half* Bb = g_vp + (size_t)bz * C_ * N_;
    const int lda = N_, ldb = N_;

    const uint32_t a_lo =
        (uint32_t)((wm * 64 + (lane & 15)) * ROW_B + (lane >> 4) * 16);
    const uint32_t b_lo =
        (uint32_t)((wn * 32 + ((lane >> 4) & 1) * 8 + (lane & 7)) * ROW_B +
                   ((lane >> 3) & 1) * 16);

    auto load_stage = [&](int slot, int kc) {
        const uint32_t abase = smb + slot * STAGE_BYTES;
        const uint32_t bbase = abase + TILE_BYTES;
        const __half* Asrc = Ab + (size_t)m0 * lda + kc * 64;
        #pragma unroll
        for (int j = 0; j < 4; j++) {
            int i = tid + j * NT;
            int row = i >> 3, kg = i & 7;
            CP_ASYNC16(abase + (uint32_t)(row * ROW_B + kg * 16),
                       Asrc + (size_t)row * lda + kg * 8);
        }
        const __half* Bsrc = Bb + (size_t)n0 * ldb + kc * 64;
        #pragma unroll
        for (int j = 0; j < 4; j++) {
            int i = tid + j * NT;
            int row = i >> 3, kg = i & 7;
            CP_ASYNC16(bbase + (uint32_t)(row * ROW_B + kg * 16),
                       Bsrc + (size_t)row * ldb + kg * 8);
        }
        CP_ASYNC_COMMIT();
    };

    GEMM_MAINLOOP(N_)

    // transposed epilogue with 1/l scaling + bias + residual
    __syncthreads();
    float* ws = sm + warp * (32 * 68);
    float bh0[4], bh1[4];
    #pragma unroll
    for (int tn = 0; tn < 4; tn++) {
        const int cb = tn * 8 + 2 * q;
        bh0[tn] = __ldg(&bias[n0 + wn * 32 + cb]);
        bh1[tn] = __ldg(&bias[n0 + wn * 32 + cb + 1]);
    }
    #pragma unroll
    for (int tm = 0; tm < 4; tm++) {
        const int r = tm * 16 + g;
        const float a0 = sm_il[wm * 64 + r];
        const float a1 = sm_il[wm * 64 + r + 8];
        #pragma unroll
        for (int tn = 0; tn < 4; tn++) {
            const int cb = tn * 8 + 2 * q;
            ws[cb * 68 + r]           = acc[tm][tn][0] * a0 + bh0[tn];
            ws[(cb + 1) * 68 + r]     = acc[tm][tn][1] * a0 + bh1[tn];
            ws[cb * 68 + r + 8]       = acc[tm][tn][2] * a1 + bh0[tn];
            ws[(cb + 1) * 68 + r + 8] = acc[tm][tn][3] * a1 + bh1[tn];
        }
    }
    __syncwarp();
    const int nbase = m0 + wm * 64;
    const int rq    = lane & 15;
    #pragma unroll
    for (int i = 0; i < 16; i++) {
        const int c  = i * 2 + (lane >> 4);
        const int cg = n0 + wn * 32 + c;
        float4 v = *reinterpret_cast<float4*>(&ws[c * 68 + rq * 4]);
        const size_t o0 = (((size_t)(bz * C_ + cg)) << 10) + nbase + rq * 4;
        float4 xv = __ldcs(reinterpret_cast<const float4*>(xr + o0));
        v.x += xv.x; v.y += xv.y; v.z += xv.z; v.w += xv.w;
        __stcs(reinterpret_cast<float4*>(Cm + o0), v);
    }
}

// ---------------- BN stats: partial sums (grid 16 x 256) ------------------
__global__ void bn_partial_kernel(const float* __restrict__ x,
                                  const float* __restrict__ wk,
                                  const float* __restrict__ wp) {
    const int sl = blockIdx.x;      // 0..15 (pair of batches)
    const int c  = blockIdx.y;      // channel
    const int tid = threadIdx.x;

    if (sl == 0) {                  // fused weight conversion on slice-0 blocks
        const int gidx = c * 256 + tid;
        #pragma unroll
        for (int i = gidx; i < C3_ * C_; i += 65536) g_wk[i] = __float2half_rn(wk[i]);
        g_wp[gidx] = __float2half_rn(wp[gidx]);
    }

    float s = 0.f, ss = 0.f;
    #pragma unroll
    for (int j = 0; j < 2; j++) {
        const int b = sl * 2 + j;
        float4 v = reinterpret_cast<const float4*>(
            x + ((size_t)b * C_ + c) * N_)[tid];
        s  += v.x + v.y + v.z + v.w;
        ss += v.x * v.x + v.y * v.y + v.z * v.z + v.w * v.w;
    }
    __shared__ float sh1[256], sh2[256];
    sh1[tid] = s; sh2[tid] = ss;
    __syncthreads();
    for (int k = 128; k > 0; k >>= 1) {
        if (tid < k) { sh1[tid] += sh1[tid + k]; sh2[tid] += sh2[tid + k]; }
        __syncthreads();
    }
    if (tid == 0) g_ps[c * 16 + sl] = make_float2(sh1[0], sh2[0]);
}

// ------- BN apply + transpose (combine folded in; fp16 vectorized) --------
__global__ __launch_bounds__(256)
void bn_apply_transpose_kernel(const float* __restrict__ x,
                               const float* __restrict__ gamma,
                               const float* __restrict__ beta) {
    __shared__ float sh[32][33];
    __shared__ float srs[32], sbe[32];
    const int b = blockIdx.z, c0 = blockIdx.y * 32, n0 = blockIdx.x * 32;
    const int tid = threadIdx.x;

    if (tid < 32) {                 // inline combine for this block's channels
        const int c = c0 + tid;
        float s = 0.f, ss = 0.f;
        #pragma unroll
        for (int t = 0; t < 16; t++) {
            float2 p = g_ps[c * 16 + t];
            s += p.x; ss += p.y;
        }
        const float inv_n = 1.0f / (float)(B_ * N_);
        const float mean = s * inv_n;
        const float var  = ss * inv_n - mean * mean;
        const float rstd = rsqrtf(var + 1e-5f);
        const float rs   = rstd * gamma[c];
        srs[tid] = rs;
        sbe[tid] = beta[c] - mean * rs;
    }
    __syncthreads();
    {
        const int tx = tid & 7;        // n-quad
        const int ty = tid >> 3;       // c
        float4 v = *reinterpret_cast<const float4*>(
            &x[((size_t)b * C_ + c0 + ty) * N_ + n0 + tx * 4]);
        const float rs = srs[ty];
        const float be = sbe[ty];
        sh[ty][tx * 4 + 0] = v.x * rs + be;
        sh[ty][tx * 4 + 1] = v.y * rs + be;
        sh[ty][tx * 4 + 2] = v.z * rs + be;
        sh[ty][tx * 4 + 3] = v.w * rs + be;
    }
    __syncthreads();
    {
        const int n  = tid >> 3;
        const int cq = tid & 7;
        __half2 h0 = __floats2half2_rn(sh[cq * 4 + 0][n], sh[cq * 4 + 1][n]);
        __half2 h1 = __floats2half2_rn(sh[cq * 4 + 2][n], sh[cq * 4 + 3][n]);
        uint2 pk;
        pk.x = *reinterpret_cast<uint32_t*>(&h0);
        pk.y = *reinterpret_cast<uint32_t*>(&h1);
        *reinterpret_cast<uint2*>(
            &g_t[((size_t)b * N_ + n0 + n) * C_ + c0 + cq * 4]) = pk;
    }
}

// ---------------- launch ----------------
extern "C" void kernel_launch(void* const* d_in, const int* in_sizes, int n_in,
                              void* d_out, int out_size) {
    const float* x      = (const float*)d_in[0];
    const float* gamma  = (const float*)d_in[1];
    const float* beta   = (const float*)d_in[2];
    const float* W_kqv  = (const float*)d_in[3];
    const float* b_kqv  = (const float*)d_in[4];
    const float* W_proj = (const float*)d_in[5];
    const float* b_proj = (const float*)d_in[6];
    float* out = (float*)d_out;

    cudaFuncSetAttribute(kqv_kernel,    cudaFuncAttributeMaxDynamicSharedMemorySize, SMEM_DYN);
    cudaFuncSetAttribute(qk_vpt_kernel, cudaFuncAttributeMaxDynamicSharedMemorySize, SMEM_DYN);
    cudaFuncSetAttribute(avp_kernel,    cudaFuncAttributeMaxDynamicSharedMemorySize, SMEM_DYN);

    // BN partials + weight conversion (combine folded into bn_apply)
    bn_partial_kernel<<<dim3(16, C_), 256>>>(x, W_kqv, W_proj);
    bn_apply_transpose_kernel<<<dim3(N_ / 32, C_ / 32, B_), 256>>>(x, gamma, beta);

    // kqv = t @ W_kqv^T + b_kqv
    kqv_kernel<<<dim3(C3_ / 128, MTOT / 128, 1), NT, SMEM_DYN>>>(b_kqv);

    // merged: g_s = exp(q k^T/16) + partials  ||  g_vp = Wp @ V^T
    qk_vpt_kernel<<<dim3(10, 8, B_), NT, SMEM_DYN>>>();

    // out = (expS @ Vp^T)^T / l + b_proj + x
    avp_kernel<<<dim3(C_ / 128, N_ / 128, B_), NT, SMEM_DYN>>>(b_proj, out, x);
}